// round 1
// baseline (speedup 1.0000x reference)
#include <cuda_runtime.h>
#include <math.h>

#define NN   100000
#define EE   500000
#define ETOT (EE + NN)
#define GG   1000

// ---------------- device scratch (static; no runtime allocation) ----------------
__device__ float d_bufA[(size_t)NN * 256];   // current node features h
__device__ float d_bufB[(size_t)NN * 256];   // linear-transform scratch (h @ W^T)
__device__ float d_as[NN];
__device__ float d_ad[NN];
__device__ int   d_rowptr[NN + 1];
__device__ int   d_cur[NN];                  // degree counter, then scatter cursor
__device__ int   d_col[ETOT];                // CSR column (src) indices, grouped by dst
__device__ float d_gsum[GG * 32];
__device__ float d_gcnt[GG];

// ---------------- MLP: x[N,1] -> 16 -> 32 -> 64 (relu each), warp per node ------
__global__ void mlp_kernel(const float* __restrict__ x,
                           const float* __restrict__ w1, const float* __restrict__ b1,
                           const float* __restrict__ w2, const float* __restrict__ b2,
                           const float* __restrict__ w3, const float* __restrict__ b3,
                           float* __restrict__ out, int n) {
    __shared__ float s_w1[16], s_b1[16];
    __shared__ float s_w2t[16 * 32];   // transposed: [k][o]
    __shared__ float s_b2[32];
    __shared__ float s_w3t[32 * 64];   // transposed: [k][o]
    __shared__ float s_b3[64];

    int tid = threadIdx.x;
    if (tid < 16) { s_w1[tid] = w1[tid]; s_b1[tid] = b1[tid]; }
    if (tid < 32) s_b2[tid] = b2[tid];
    if (tid < 64) s_b3[tid] = b3[tid];
    for (int idx = tid; idx < 32 * 16; idx += blockDim.x) {
        int o = idx / 16, k = idx % 16;
        s_w2t[k * 32 + o] = w2[idx];
    }
    for (int idx = tid; idx < 64 * 32; idx += blockDim.x) {
        int o = idx / 32, k = idx % 32;
        s_w3t[k * 64 + o] = w3[idx];
    }
    __syncthreads();

    int warp = (blockIdx.x * blockDim.x + tid) >> 5;
    int lane = tid & 31;
    if (warp >= n) return;

    float xv = x[warp];
    float h1[16];
#pragma unroll
    for (int j = 0; j < 16; j++) {
        float v = s_w1[j] * xv + s_b1[j];
        h1[j] = v > 0.f ? v : 0.f;
    }
    // layer 2: lane `lane` owns hidden unit `lane` (32 units == 32 lanes)
    float h2;
    {
        float acc = s_b2[lane];
#pragma unroll
        for (int k = 0; k < 16; k++) acc += s_w2t[k * 32 + lane] * h1[k];
        h2 = acc > 0.f ? acc : 0.f;
    }
    // layer 3: 64 outputs, lane handles lane and lane+32
#pragma unroll
    for (int j2 = 0; j2 < 2; j2++) {
        int j = lane + 32 * j2;
        float acc = s_b3[j];
#pragma unroll
        for (int k = 0; k < 32; k++)
            acc += __shfl_sync(0xffffffffu, h2, k) * s_w3t[k * 64 + j];
        out[(size_t)warp * 64 + j] = acc > 0.f ? acc : 0.f;
    }
}

// ---------------- CSR build (dst -> list of src), self-loops included -----------
__global__ void init_deg_kernel(int n) {
    int i = blockIdx.x * blockDim.x + threadIdx.x;
    if (i < n) d_cur[i] = 1;   // self loop
}
__global__ void count_deg_kernel(const int* __restrict__ dst, int E) {
    int e = blockIdx.x * blockDim.x + threadIdx.x;
    if (e < E) atomicAdd(&d_cur[dst[e]], 1);
}
// single-block exclusive scan of d_cur -> d_rowptr (n up to 100000)
__global__ void scan_kernel(int n) {
    __shared__ int sh[1024];
    __shared__ int carry;
    if (threadIdx.x == 0) carry = 0;
    __syncthreads();
    for (int base = 0; base < n; base += 1024) {
        int i = base + (int)threadIdx.x;
        int v = (i < n) ? d_cur[i] : 0;
        sh[threadIdx.x] = v;
        __syncthreads();
        for (int off = 1; off < 1024; off <<= 1) {
            int t = 0;
            if ((int)threadIdx.x >= off) t = sh[threadIdx.x - off];
            __syncthreads();
            sh[threadIdx.x] += t;
            __syncthreads();
        }
        if (i < n) d_rowptr[i] = carry + sh[threadIdx.x] - v;  // exclusive
        __syncthreads();
        if (threadIdx.x == 0) carry += sh[1023];
        __syncthreads();
    }
    if (threadIdx.x == 0) d_rowptr[n] = carry;
}
__global__ void fill_self_kernel(int n) {
    int i = blockIdx.x * blockDim.x + threadIdx.x;
    if (i < n) {
        int r = d_rowptr[i];
        d_col[r] = i;       // self loop first
        d_cur[i] = r + 1;   // cursor for remaining edges
    }
}
__global__ void scatter_edges_kernel(const int* __restrict__ src,
                                     const int* __restrict__ dst, int E) {
    int e = blockIdx.x * blockDim.x + threadIdx.x;
    if (e < E) {
        int p = atomicAdd(&d_cur[dst[e]], 1);
        d_col[p] = src[e];
    }
}

// ---------------- SGEMM: C[n,O] = A[n,I] @ W[O,I]^T ------------------------------
// 64x64 tile, BK=16, 256 threads, 4x4 register micro-tile.
__global__ void gemm_nt_kernel(const float* __restrict__ A, const float* __restrict__ W,
                               float* __restrict__ C, int n, int I, int O) {
    __shared__ float As[16][64];
    __shared__ float Bs[16][64];
    int bm = blockIdx.y * 64;
    int bn = blockIdx.x * 64;
    int tid = threadIdx.x;
    int tx = tid % 16, ty = tid / 16;
    int lr = tid >> 2;           // 0..63 : row of tile being loaded
    int lk = (tid & 3) * 4;      // 0,4,8,12 : k offset (float4)
    float acc[4][4];
#pragma unroll
    for (int i = 0; i < 4; i++)
#pragma unroll
        for (int j = 0; j < 4; j++) acc[i][j] = 0.f;

    int arow = bm + lr;
    int brow = bn + lr;
    for (int k0 = 0; k0 < I; k0 += 16) {
        float4 av = make_float4(0.f, 0.f, 0.f, 0.f);
        float4 bv = make_float4(0.f, 0.f, 0.f, 0.f);
        if (arow < n) av = *(const float4*)(A + (size_t)arow * I + k0 + lk);
        if (brow < O) bv = *(const float4*)(W + (size_t)brow * I + k0 + lk);
        As[lk + 0][lr] = av.x; As[lk + 1][lr] = av.y;
        As[lk + 2][lr] = av.z; As[lk + 3][lr] = av.w;
        Bs[lk + 0][lr] = bv.x; Bs[lk + 1][lr] = bv.y;
        Bs[lk + 2][lr] = bv.z; Bs[lk + 3][lr] = bv.w;
        __syncthreads();
#pragma unroll
        for (int k = 0; k < 16; k++) {
            float am[4], bnv[4];
#pragma unroll
            for (int i = 0; i < 4; i++) am[i] = As[k][ty * 4 + i];
#pragma unroll
            for (int j = 0; j < 4; j++) bnv[j] = Bs[k][tx * 4 + j];
#pragma unroll
            for (int i = 0; i < 4; i++)
#pragma unroll
                for (int j = 0; j < 4; j++) acc[i][j] += am[i] * bnv[j];
        }
        __syncthreads();
    }
#pragma unroll
    for (int i = 0; i < 4; i++) {
        int r = bm + ty * 4 + i;
        if (r >= n) continue;
#pragma unroll
        for (int j = 0; j < 4; j++) {
            int c = bn + tx * 4 + j;
            if (c < O) C[(size_t)r * O + c] = acc[i][j];
        }
    }
}

// ---------------- alpha_src / alpha_dst per node (warp per row) ------------------
__global__ void alpha_kernel(const float* __restrict__ h, const float* __restrict__ a_s,
                             const float* __restrict__ a_d, int n, int O) {
    int warp = (blockIdx.x * blockDim.x + threadIdx.x) >> 5;
    int lane = threadIdx.x & 31;
    if (warp >= n) return;
    const float* row = h + (size_t)warp * O;
    float sa = 0.f, sd = 0.f;
    for (int c = lane; c < O; c += 32) {
        float hv = row[c];
        sa += hv * a_s[c];
        sd += hv * a_d[c];
    }
#pragma unroll
    for (int o = 16; o; o >>= 1) {
        sa += __shfl_xor_sync(0xffffffffu, sa, o);
        sd += __shfl_xor_sync(0xffffffffu, sd, o);
    }
    if (lane == 0) { d_as[warp] = sa; d_ad[warp] = sd; }
}

// ---------------- GAT aggregate: warp per dst node, CSR gather -------------------
template <int CPL>   // channels per lane = O/32
__global__ void gat_agg_kernel(const float* __restrict__ hlin,
                               const float* __restrict__ bias,
                               float* __restrict__ out, int n, int O) {
    int warp = (blockIdx.x * blockDim.x + threadIdx.x) >> 5;
    int lane = threadIdx.x & 31;
    if (warp >= n) return;
    int s = d_rowptr[warp];
    int e = d_rowptr[warp + 1];
    float adi = d_ad[warp];

    // pass 1: segment max of leaky_relu(as[src] + ad[dst])
    float m = -1e30f;
    for (int p = s + lane; p < e; p += 32) {
        float v = d_as[d_col[p]] + adi;
        v = v > 0.f ? v : 0.2f * v;
        m = fmaxf(m, v);
    }
#pragma unroll
    for (int o = 16; o; o >>= 1) m = fmaxf(m, __shfl_xor_sync(0xffffffffu, m, o));

    // pass 2: unnormalized weighted sum + denominator
    float den = 0.f;
    float acc[CPL];
#pragma unroll
    for (int c = 0; c < CPL; c++) acc[c] = 0.f;

    for (int p0 = s; p0 < e; p0 += 32) {
        int p = p0 + lane;
        float w = 0.f;
        int src = 0;
        if (p < e) {
            src = d_col[p];
            float v = d_as[src] + adi;
            v = v > 0.f ? v : 0.2f * v;
            w = __expf(v - m);
            den += w;
        }
        int cnt = min(32, e - p0);
        for (int q = 0; q < cnt; q++) {
            float wq = __shfl_sync(0xffffffffu, w, q);
            int   sq = __shfl_sync(0xffffffffu, src, q);
            const float* row = hlin + (size_t)sq * O;
#pragma unroll
            for (int c = 0; c < CPL; c++) acc[c] += wq * row[lane + 32 * c];
        }
    }
#pragma unroll
    for (int o = 16; o; o >>= 1) den += __shfl_xor_sync(0xffffffffu, den, o);
    float inv = 1.f / den;   // den >= exp(max - m) >= ... >= 1 term always exists (self loop)
#pragma unroll
    for (int c = 0; c < CPL; c++) {
        int ch = lane + 32 * c;
        float v = acc[c] * inv + bias[ch];
        out[(size_t)warp * O + ch] = v > 0.f ? v : 0.f;   // relu after GAT layer
    }
}

// ---------------- mean pooling over sorted batch + final linear+sigmoid ----------
__global__ void zero_pool_kernel() {
    int i = blockIdx.x * blockDim.x + threadIdx.x;
    if (i < GG * 32) d_gsum[i] = 0.f;
    if (i < GG) d_gcnt[i] = 0.f;
}
__global__ void pool_kernel(const float* __restrict__ h, const int* __restrict__ batch,
                            int n) {
    int warp = (blockIdx.x * blockDim.x + threadIdx.x) >> 5;
    int lane = threadIdx.x & 31;
    if (warp >= n) return;
    int b = batch[warp];
    atomicAdd(&d_gsum[b * 32 + lane], h[(size_t)warp * 32 + lane]);
    if (lane == 0) atomicAdd(&d_gcnt[b], 1.f);
}
__global__ void final_kernel(const float* __restrict__ lw, const float* __restrict__ lb,
                             float* __restrict__ out) {
    int g = blockIdx.x * blockDim.x + threadIdx.x;
    if (g >= GG) return;
    float cnt = fmaxf(d_gcnt[g], 1.f);
    float acc = lb[0];
#pragma unroll
    for (int c = 0; c < 32; c++) acc += (d_gsum[g * 32 + c] / cnt) * lw[c];
    out[g] = 1.f / (1.f + __expf(-acc));
}

// ---------------- launch ----------------------------------------------------------
extern "C" void kernel_launch(void* const* d_in, const int* in_sizes, int n_in,
                              void* d_out, int out_size) {
    const float* x     = (const float*)d_in[0];
    const int*   ei    = (const int*)d_in[1];
    const int*   batch = (const int*)d_in[2];
    const float* w1 = (const float*)d_in[3]; const float* b1 = (const float*)d_in[4];
    const float* w2 = (const float*)d_in[5]; const float* b2 = (const float*)d_in[6];
    const float* w3 = (const float*)d_in[7]; const float* b3 = (const float*)d_in[8];
    float* out = (float*)d_out;

    int n = in_sizes[0];          // 100000 (x is [N,1])
    int E = in_sizes[1] / 2;      // 500000
    const int* src = ei;          // edge_index[0]
    const int* dst = ei + E;      // edge_index[1]

    float* bufA; float* bufB;
    cudaGetSymbolAddress((void**)&bufA, d_bufA);
    cudaGetSymbolAddress((void**)&bufB, d_bufB);

    const int TPB = 256;
    int warpBlocks = (n * 32 + TPB - 1) / TPB;   // warp-per-node kernels

    // 1) MLP feature extractor -> bufA [n,64]
    mlp_kernel<<<warpBlocks, TPB>>>(x, w1, b1, w2, b2, w3, b3, bufA, n);

    // 2) CSR build (shared by all 5 GAT layers)
    init_deg_kernel<<<(n + TPB - 1) / TPB, TPB>>>(n);
    count_deg_kernel<<<(E + TPB - 1) / TPB, TPB>>>(dst, E);
    scan_kernel<<<1, 1024>>>(n);
    fill_self_kernel<<<(n + TPB - 1) / TPB, TPB>>>(n);
    scatter_edges_kernel<<<(E + TPB - 1) / TPB, TPB>>>(src, dst, E);

    // 3) five GAT layers
    struct Layer { const float *W, *as_, *ad_, *b; int I, O; };
    Layer L[5] = {
        { (const float*)d_in[9],  (const float*)d_in[10], (const float*)d_in[11], (const float*)d_in[12],  64, 128 },
        { (const float*)d_in[13], (const float*)d_in[14], (const float*)d_in[15], (const float*)d_in[16], 128, 256 },
        { (const float*)d_in[17], (const float*)d_in[18], (const float*)d_in[19], (const float*)d_in[20], 256, 128 },
        { (const float*)d_in[21], (const float*)d_in[22], (const float*)d_in[23], (const float*)d_in[24], 128,  64 },
        { (const float*)d_in[25], (const float*)d_in[26], (const float*)d_in[27], (const float*)d_in[28],  64,  32 },
    };

    for (int l = 0; l < 5; l++) {
        int I = L[l].I, O = L[l].O;
        dim3 grid((O + 63) / 64, (n + 63) / 64);
        gemm_nt_kernel<<<grid, 256>>>(bufA, L[l].W, bufB, n, I, O);
        alpha_kernel<<<warpBlocks, TPB>>>(bufB, L[l].as_, L[l].ad_, n, O);
        switch (O >> 5) {
            case 1: gat_agg_kernel<1><<<warpBlocks, TPB>>>(bufB, L[l].b, bufA, n, O); break;
            case 2: gat_agg_kernel<2><<<warpBlocks, TPB>>>(bufB, L[l].b, bufA, n, O); break;
            case 4: gat_agg_kernel<4><<<warpBlocks, TPB>>>(bufB, L[l].b, bufA, n, O); break;
            case 8: gat_agg_kernel<8><<<warpBlocks, TPB>>>(bufB, L[l].b, bufA, n, O); break;
        }
    }

    // 4) global mean pool + final linear + sigmoid
    zero_pool_kernel<<<(GG * 32 + TPB - 1) / TPB, TPB>>>();
    pool_kernel<<<warpBlocks, TPB>>>(bufA, batch, n);
    final_kernel<<<(GG + TPB - 1) / TPB, TPB>>>((const float*)d_in[29],
                                                (const float*)d_in[30], out);
}

// round 2
// speedup vs baseline: 1.3524x; 1.3524x over previous
#include <cuda_runtime.h>
#include <mma.h>
#include <math.h>

using namespace nvcuda;

#define NN   100000
#define EE   500000
#define ETOT (EE + NN)
#define GG   1000

// ---------------- device scratch (static; no runtime allocation) ----------------
__device__ float d_bufA[(size_t)NN * 256];   // current node features h
__device__ float d_bufB[(size_t)NN * 256];   // linear-transform scratch (h @ W^T)
__device__ float d_as[NN];
__device__ float d_ad[NN];
__device__ int   d_rowptr[NN + 1];
__device__ int   d_cur[NN];                  // degree counter, then scatter cursor
__device__ int   d_col[ETOT];                // CSR column (src) indices, grouped by dst
__device__ float d_gsum[GG * 32];
__device__ float d_gcnt[GG];
__device__ int   d_blocksum[160];
__device__ int   d_total;

// ---------------- MLP: x[N,1] -> 16 -> 32 -> 64 (relu each), warp per node ------
__global__ void mlp_kernel(const float* __restrict__ x,
                           const float* __restrict__ w1, const float* __restrict__ b1,
                           const float* __restrict__ w2, const float* __restrict__ b2,
                           const float* __restrict__ w3, const float* __restrict__ b3,
                           float* __restrict__ out, int n) {
    __shared__ float s_w1[16], s_b1[16];
    __shared__ float s_w2t[16 * 32];   // transposed: [k][o]
    __shared__ float s_b2[32];
    __shared__ float s_w3t[32 * 64];   // transposed: [k][o]
    __shared__ float s_b3[64];

    int tid = threadIdx.x;
    if (tid < 16) { s_w1[tid] = w1[tid]; s_b1[tid] = b1[tid]; }
    if (tid < 32) s_b2[tid] = b2[tid];
    if (tid < 64) s_b3[tid] = b3[tid];
    for (int idx = tid; idx < 32 * 16; idx += blockDim.x) {
        int o = idx / 16, k = idx % 16;
        s_w2t[k * 32 + o] = w2[idx];
    }
    for (int idx = tid; idx < 64 * 32; idx += blockDim.x) {
        int o = idx / 32, k = idx % 32;
        s_w3t[k * 64 + o] = w3[idx];
    }
    __syncthreads();

    int warp = (blockIdx.x * blockDim.x + tid) >> 5;
    int lane = tid & 31;
    if (warp >= n) return;

    float xv = x[warp];
    float h1[16];
#pragma unroll
    for (int j = 0; j < 16; j++) {
        float v = s_w1[j] * xv + s_b1[j];
        h1[j] = v > 0.f ? v : 0.f;
    }
    float h2;
    {
        float acc = s_b2[lane];
#pragma unroll
        for (int k = 0; k < 16; k++) acc += s_w2t[k * 32 + lane] * h1[k];
        h2 = acc > 0.f ? acc : 0.f;
    }
#pragma unroll
    for (int j2 = 0; j2 < 2; j2++) {
        int j = lane + 32 * j2;
        float acc = s_b3[j];
#pragma unroll
        for (int k = 0; k < 32; k++)
            acc += __shfl_sync(0xffffffffu, h2, k) * s_w3t[k * 64 + j];
        out[(size_t)warp * 64 + j] = acc > 0.f ? acc : 0.f;
    }
}

// ---------------- CSR build (dst -> list of src), self-loops included -----------
__global__ void init_deg_kernel(int n) {
    int i = blockIdx.x * blockDim.x + threadIdx.x;
    if (i < n) d_cur[i] = 1;   // self loop
}
__global__ void count_deg_kernel(const int* __restrict__ dst, int E) {
    int e = blockIdx.x * blockDim.x + threadIdx.x;
    if (e < E) atomicAdd(&d_cur[dst[e]], 1);
}

// -------- multi-block exclusive scan: phase 1 (per-block scan + block sums) -----
__global__ void scan_block_kernel(int n) {
    __shared__ int warpsum[32];
    int i = blockIdx.x * 1024 + threadIdx.x;
    int lane = threadIdx.x & 31, wid = threadIdx.x >> 5;
    int v = (i < n) ? d_cur[i] : 0;
    int x = v;
#pragma unroll
    for (int o = 1; o < 32; o <<= 1) {
        int t = __shfl_up_sync(0xffffffffu, x, o);
        if (lane >= o) x += t;
    }
    if (lane == 31) warpsum[wid] = x;
    __syncthreads();
    if (wid == 0) {
        int s = warpsum[lane];
#pragma unroll
        for (int o = 1; o < 32; o <<= 1) {
            int t = __shfl_up_sync(0xffffffffu, s, o);
            if (lane >= o) s += t;
        }
        warpsum[lane] = s;
    }
    __syncthreads();
    int base = wid ? warpsum[wid - 1] : 0;
    int incl = base + x;
    if (i < n) d_rowptr[i] = incl - v;   // exclusive within block
    if (threadIdx.x == 1023) d_blocksum[blockIdx.x] = incl;
}
// phase 2: scan <=128 block sums in a single block of 128 threads
__global__ void scan_sums_kernel(int nb) {
    __shared__ int ws[4];
    int lane = threadIdx.x & 31, wid = threadIdx.x >> 5;
    int v = ((int)threadIdx.x < nb) ? d_blocksum[threadIdx.x] : 0;
    int x = v;
#pragma unroll
    for (int o = 1; o < 32; o <<= 1) {
        int t = __shfl_up_sync(0xffffffffu, x, o);
        if (lane >= o) x += t;
    }
    if (lane == 31) ws[wid] = x;
    __syncthreads();
    int add = 0;
    for (int w0 = 0; w0 < wid; w0++) add += ws[w0];
    int incl = add + x;
    d_blocksum[threadIdx.x] = incl - v;   // exclusive offsets (>=nb holds total)
    if ((int)threadIdx.x == nb - 1) d_total = incl;
}
// phase 3: add offsets; also write rowptr[n]
__global__ void scan_add_kernel(int n) {
    int i = blockIdx.x * 1024 + threadIdx.x;
    if (i < n) d_rowptr[i] += d_blocksum[blockIdx.x];
    else if (i == n) d_rowptr[n] = d_total;
}

__global__ void fill_self_kernel(int n) {
    int i = blockIdx.x * blockDim.x + threadIdx.x;
    if (i < n) {
        int r = d_rowptr[i];
        d_col[r] = i;       // self loop first
        d_cur[i] = r + 1;   // cursor for remaining edges
    }
}
__global__ void scatter_edges_kernel(const int* __restrict__ src,
                                     const int* __restrict__ dst, int E) {
    int e = blockIdx.x * blockDim.x + threadIdx.x;
    if (e < E) {
        int p = atomicAdd(&d_cur[dst[e]], 1);
        d_col[p] = src[e];
    }
}

// ---------------- TF32 tensor-core GEMM: C[n,O] = A[n,I] @ W[O,I]^T --------------
// 64x64 block tile, BK=16, 256 threads = 8 warps (4 m-rows x 2 n-cols),
// each warp computes 16x32 via two m16n16k8 wmma accumulators.
#define GLD 20   // padded smem row stride (floats), multiple of 4
__global__ void gemm_tf32_kernel(const float* __restrict__ A, const float* __restrict__ W,
                                 float* __restrict__ C, int n, int I, int O) {
    __shared__ float As[64 * GLD];
    __shared__ float Bs[64 * GLD];
    int tid = threadIdx.x;
    int w = tid >> 5;
    int wm = w & 3, wn = w >> 2;
    int bm = blockIdx.y * 64, bn = blockIdx.x * 64;

    wmma::fragment<wmma::accumulator, 16, 16, 8, float> acc0, acc1;
    wmma::fill_fragment(acc0, 0.f);
    wmma::fill_fragment(acc1, 0.f);

    int lr = tid >> 2;           // 0..63 row
    int lk = (tid & 3) * 4;      // 0,4,8,12

    int arow = bm + lr;
    int brow = bn + lr;
    for (int k0 = 0; k0 < I; k0 += 16) {
        float4 av = make_float4(0.f, 0.f, 0.f, 0.f);
        float4 bv = make_float4(0.f, 0.f, 0.f, 0.f);
        if (arow < n) av = *(const float4*)(A + (size_t)arow * I + k0 + lk);
        if (brow < O) bv = *(const float4*)(W + (size_t)brow * I + k0 + lk);
        *(float4*)(As + lr * GLD + lk) = av;
        *(float4*)(Bs + lr * GLD + lk) = bv;
        __syncthreads();
#pragma unroll
        for (int kk = 0; kk < 16; kk += 8) {
            wmma::fragment<wmma::matrix_a, 16, 16, 8, wmma::precision::tf32, wmma::row_major> af;
            wmma::load_matrix_sync(af, As + (wm * 16) * GLD + kk, GLD);
#pragma unroll
            for (int t = 0; t < af.num_elements; t++) af.x[t] = wmma::__float_to_tf32(af.x[t]);

            wmma::fragment<wmma::matrix_b, 16, 16, 8, wmma::precision::tf32, wmma::col_major> bf0, bf1;
            wmma::load_matrix_sync(bf0, Bs + (wn * 32) * GLD + kk, GLD);
            wmma::load_matrix_sync(bf1, Bs + (wn * 32 + 16) * GLD + kk, GLD);
#pragma unroll
            for (int t = 0; t < bf0.num_elements; t++) {
                bf0.x[t] = wmma::__float_to_tf32(bf0.x[t]);
                bf1.x[t] = wmma::__float_to_tf32(bf1.x[t]);
            }
            wmma::mma_sync(acc0, af, bf0, acc0);
            wmma::mma_sync(acc1, af, bf1, acc1);
        }
        __syncthreads();
    }
    int r0 = bm + wm * 16;
    if (r0 < n) {   // n % 16 == 0 -> tile fully valid if start valid
        int c0 = bn + wn * 32;
        if (c0 < O)
            wmma::store_matrix_sync(C + (size_t)r0 * O + c0, acc0, O, wmma::mem_row_major);
        if (c0 + 16 < O)
            wmma::store_matrix_sync(C + (size_t)r0 * O + c0 + 16, acc1, O, wmma::mem_row_major);
    }
}

// ---------------- alpha_src / alpha_dst per node (warp per row) ------------------
__global__ void alpha_kernel(const float* __restrict__ h, const float* __restrict__ a_s,
                             const float* __restrict__ a_d, int n, int O) {
    int warp = (blockIdx.x * blockDim.x + threadIdx.x) >> 5;
    int lane = threadIdx.x & 31;
    if (warp >= n) return;
    const float* row = h + (size_t)warp * O;
    float sa = 0.f, sd = 0.f;
    for (int c = lane; c < O; c += 32) {
        float hv = row[c];
        sa += hv * a_s[c];
        sd += hv * a_d[c];
    }
#pragma unroll
    for (int o = 16; o; o >>= 1) {
        sa += __shfl_xor_sync(0xffffffffu, sa, o);
        sd += __shfl_xor_sync(0xffffffffu, sd, o);
    }
    if (lane == 0) { d_as[warp] = sa; d_ad[warp] = sd; }
}

// ---------------- GAT aggregate: warp per dst node, CSR gather -------------------
template <int CPL>   // channels per lane = O/32
__global__ void gat_agg_kernel(const float* __restrict__ hlin,
                               const float* __restrict__ bias,
                               float* __restrict__ out, int n, int O) {
    int warp = (blockIdx.x * blockDim.x + threadIdx.x) >> 5;
    int lane = threadIdx.x & 31;
    if (warp >= n) return;
    int s = d_rowptr[warp];
    int e = d_rowptr[warp + 1];
    float adi = d_ad[warp];

    float m = -1e30f;
    for (int p = s + lane; p < e; p += 32) {
        float v = d_as[d_col[p]] + adi;
        v = v > 0.f ? v : 0.2f * v;
        m = fmaxf(m, v);
    }
#pragma unroll
    for (int o = 16; o; o >>= 1) m = fmaxf(m, __shfl_xor_sync(0xffffffffu, m, o));

    float den = 0.f;
    float acc[CPL];
#pragma unroll
    for (int c = 0; c < CPL; c++) acc[c] = 0.f;

    for (int p0 = s; p0 < e; p0 += 32) {
        int p = p0 + lane;
        float w = 0.f;
        int src = 0;
        if (p < e) {
            src = d_col[p];
            float v = d_as[src] + adi;
            v = v > 0.f ? v : 0.2f * v;
            w = __expf(v - m);
            den += w;
        }
        int cnt = min(32, e - p0);
        for (int q = 0; q < cnt; q++) {
            float wq = __shfl_sync(0xffffffffu, w, q);
            int   sq = __shfl_sync(0xffffffffu, src, q);
            const float* row = hlin + (size_t)sq * O;
#pragma unroll
            for (int c = 0; c < CPL; c++) acc[c] += wq * row[lane + 32 * c];
        }
    }
#pragma unroll
    for (int o = 16; o; o >>= 1) den += __shfl_xor_sync(0xffffffffu, den, o);
    float inv = 1.f / den;
#pragma unroll
    for (int c = 0; c < CPL; c++) {
        int ch = lane + 32 * c;
        float v = acc[c] * inv + bias[ch];
        out[(size_t)warp * O + ch] = v > 0.f ? v : 0.f;
    }
}

// ---------------- mean pooling over sorted batch + final linear+sigmoid ----------
__global__ void zero_pool_kernel() {
    int i = blockIdx.x * blockDim.x + threadIdx.x;
    if (i < GG * 32) d_gsum[i] = 0.f;
    if (i < GG) d_gcnt[i] = 0.f;
}
__global__ void pool_kernel(const float* __restrict__ h, const int* __restrict__ batch,
                            int n) {
    int warp = (blockIdx.x * blockDim.x + threadIdx.x) >> 5;
    int lane = threadIdx.x & 31;
    if (warp >= n) return;
    int b = batch[warp];
    atomicAdd(&d_gsum[b * 32 + lane], h[(size_t)warp * 32 + lane]);
    if (lane == 0) atomicAdd(&d_gcnt[b], 1.f);
}
__global__ void final_kernel(const float* __restrict__ lw, const float* __restrict__ lb,
                             float* __restrict__ out) {
    int g = blockIdx.x * blockDim.x + threadIdx.x;
    if (g >= GG) return;
    float cnt = fmaxf(d_gcnt[g], 1.f);
    float acc = lb[0];
#pragma unroll
    for (int c = 0; c < 32; c++) acc += (d_gsum[g * 32 + c] / cnt) * lw[c];
    out[g] = 1.f / (1.f + __expf(-acc));
}

// ---------------- launch ----------------------------------------------------------
extern "C" void kernel_launch(void* const* d_in, const int* in_sizes, int n_in,
                              void* d_out, int out_size) {
    const float* x     = (const float*)d_in[0];
    const int*   ei    = (const int*)d_in[1];
    const int*   batch = (const int*)d_in[2];
    const float* w1 = (const float*)d_in[3]; const float* b1 = (const float*)d_in[4];
    const float* w2 = (const float*)d_in[5]; const float* b2 = (const float*)d_in[6];
    const float* w3 = (const float*)d_in[7]; const float* b3 = (const float*)d_in[8];
    float* out = (float*)d_out;

    int n = in_sizes[0];          // 100000 (x is [N,1])
    int E = in_sizes[1] / 2;      // 500000
    const int* src = ei;          // edge_index[0]
    const int* dst = ei + E;      // edge_index[1]

    float* bufA; float* bufB;
    cudaGetSymbolAddress((void**)&bufA, d_bufA);
    cudaGetSymbolAddress((void**)&bufB, d_bufB);

    const int TPB = 256;
    int warpBlocks = (n * 32 + TPB - 1) / TPB;   // warp-per-node kernels

    // 1) MLP feature extractor -> bufA [n,64]
    mlp_kernel<<<warpBlocks, TPB>>>(x, w1, b1, w2, b2, w3, b3, bufA, n);

    // 2) CSR build (shared by all 5 GAT layers)
    init_deg_kernel<<<(n + TPB - 1) / TPB, TPB>>>(n);
    count_deg_kernel<<<(E + TPB - 1) / TPB, TPB>>>(dst, E);
    int nb = (n + 1023) / 1024;
    scan_block_kernel<<<nb, 1024>>>(n);
    scan_sums_kernel<<<1, 128>>>(nb);
    scan_add_kernel<<<(n + 1024) / 1024, 1024>>>(n);
    fill_self_kernel<<<(n + TPB - 1) / TPB, TPB>>>(n);
    scatter_edges_kernel<<<(E + TPB - 1) / TPB, TPB>>>(src, dst, E);

    // 3) five GAT layers
    struct Layer { const float *W, *as_, *ad_, *b; int I, O; };
    Layer L[5] = {
        { (const float*)d_in[9],  (const float*)d_in[10], (const float*)d_in[11], (const float*)d_in[12],  64, 128 },
        { (const float*)d_in[13], (const float*)d_in[14], (const float*)d_in[15], (const float*)d_in[16], 128, 256 },
        { (const float*)d_in[17], (const float*)d_in[18], (const float*)d_in[19], (const float*)d_in[20], 256, 128 },
        { (const float*)d_in[21], (const float*)d_in[22], (const float*)d_in[23], (const float*)d_in[24], 128,  64 },
        { (const float*)d_in[25], (const float*)d_in[26], (const float*)d_in[27], (const float*)d_in[28],  64,  32 },
    };

    for (int l = 0; l < 5; l++) {
        int I = L[l].I, O = L[l].O;
        dim3 grid((O + 63) / 64, (n + 63) / 64);
        gemm_tf32_kernel<<<grid, 256>>>(bufA, L[l].W, bufB, n, I, O);
        alpha_kernel<<<warpBlocks, TPB>>>(bufB, L[l].as_, L[l].ad_, n, O);
        switch (O >> 5) {
            case 1: gat_agg_kernel<1><<<warpBlocks, TPB>>>(bufB, L[l].b, bufA, n, O); break;
            case 2: gat_agg_kernel<2><<<warpBlocks, TPB>>>(bufB, L[l].b, bufA, n, O); break;
            case 4: gat_agg_kernel<4><<<warpBlocks, TPB>>>(bufB, L[l].b, bufA, n, O); break;
            case 8: gat_agg_kernel<8><<<warpBlocks, TPB>>>(bufB, L[l].b, bufA, n, O); break;
        }
    }

    // 4) global mean pool + final linear + sigmoid
    zero_pool_kernel<<<(GG * 32 + TPB - 1) / TPB, TPB>>>();
    pool_kernel<<<warpBlocks, TPB>>>(bufA, batch, n);
    final_kernel<<<(GG + TPB - 1) / TPB, TPB>>>((const float*)d_in[29],
                                                (const float*)d_in[30], out);
}

// round 3
// speedup vs baseline: 1.4130x; 1.0448x over previous
#include <cuda_runtime.h>
#include <mma.h>
#include <math.h>

using namespace nvcuda;

#define NN   100000
#define EE   500000
#define ETOT (EE + NN)
#define GG   1000

// ---------------- device scratch (static; no runtime allocation) ----------------
__device__ float d_bufA[(size_t)NN * 256];
__device__ float d_bufB[(size_t)NN * 256];
__device__ float d_as[NN];
__device__ float d_ad[NN];
__device__ int   d_rowptr[NN + 1];
__device__ int   d_cur[NN];
__device__ int   d_col[ETOT];
__device__ float d_gsum[GG * 32];
__device__ float d_gcnt[GG];
__device__ int   d_blocksum[160];
__device__ int   d_total;

// ---------------- MLP: x[N,1] -> 16 -> 32 -> 64 (relu each), warp per node ------
__global__ void mlp_kernel(const float* __restrict__ x,
                           const float* __restrict__ w1, const float* __restrict__ b1,
                           const float* __restrict__ w2, const float* __restrict__ b2,
                           const float* __restrict__ w3, const float* __restrict__ b3,
                           float* __restrict__ out, int n) {
    __shared__ float s_w1[16], s_b1[16];
    __shared__ float s_w2t[16 * 32];
    __shared__ float s_b2[32];
    __shared__ float s_w3t[32 * 64];
    __shared__ float s_b3[64];

    int tid = threadIdx.x;
    if (tid < 16) { s_w1[tid] = w1[tid]; s_b1[tid] = b1[tid]; }
    if (tid < 32) s_b2[tid] = b2[tid];
    if (tid < 64) s_b3[tid] = b3[tid];
    for (int idx = tid; idx < 32 * 16; idx += blockDim.x) {
        int o = idx / 16, k = idx % 16;
        s_w2t[k * 32 + o] = w2[idx];
    }
    for (int idx = tid; idx < 64 * 32; idx += blockDim.x) {
        int o = idx / 32, k = idx % 32;
        s_w3t[k * 64 + o] = w3[idx];
    }
    __syncthreads();

    int warp = (blockIdx.x * blockDim.x + tid) >> 5;
    int lane = tid & 31;
    if (warp >= n) return;

    float xv = x[warp];
    float h1[16];
#pragma unroll
    for (int j = 0; j < 16; j++) {
        float v = s_w1[j] * xv + s_b1[j];
        h1[j] = v > 0.f ? v : 0.f;
    }
    float h2;
    {
        float acc = s_b2[lane];
#pragma unroll
        for (int k = 0; k < 16; k++) acc += s_w2t[k * 32 + lane] * h1[k];
        h2 = acc > 0.f ? acc : 0.f;
    }
#pragma unroll
    for (int j2 = 0; j2 < 2; j2++) {
        int j = lane + 32 * j2;
        float acc = s_b3[j];
#pragma unroll
        for (int k = 0; k < 32; k++)
            acc += __shfl_sync(0xffffffffu, h2, k) * s_w3t[k * 64 + j];
        out[(size_t)warp * 64 + j] = acc > 0.f ? acc : 0.f;
    }
}

// ---------------- CSR build (dst -> list of src), self-loops included -----------
__global__ void init_deg_kernel(int n) {
    int i = blockIdx.x * blockDim.x + threadIdx.x;
    if (i < n) d_cur[i] = 1;
}
__global__ void count_deg_kernel(const int* __restrict__ dst, int E) {
    int e = blockIdx.x * blockDim.x + threadIdx.x;
    if (e < E) atomicAdd(&d_cur[dst[e]], 1);
}
__global__ void scan_block_kernel(int n) {
    __shared__ int warpsum[32];
    int i = blockIdx.x * 1024 + threadIdx.x;
    int lane = threadIdx.x & 31, wid = threadIdx.x >> 5;
    int v = (i < n) ? d_cur[i] : 0;
    int x = v;
#pragma unroll
    for (int o = 1; o < 32; o <<= 1) {
        int t = __shfl_up_sync(0xffffffffu, x, o);
        if (lane >= o) x += t;
    }
    if (lane == 31) warpsum[wid] = x;
    __syncthreads();
    if (wid == 0) {
        int s = warpsum[lane];
#pragma unroll
        for (int o = 1; o < 32; o <<= 1) {
            int t = __shfl_up_sync(0xffffffffu, s, o);
            if (lane >= o) s += t;
        }
        warpsum[lane] = s;
    }
    __syncthreads();
    int base = wid ? warpsum[wid - 1] : 0;
    int incl = base + x;
    if (i < n) d_rowptr[i] = incl - v;
    if (threadIdx.x == 1023) d_blocksum[blockIdx.x] = incl;
}
__global__ void scan_sums_kernel(int nb) {
    __shared__ int ws[4];
    int lane = threadIdx.x & 31, wid = threadIdx.x >> 5;
    int v = ((int)threadIdx.x < nb) ? d_blocksum[threadIdx.x] : 0;
    int x = v;
#pragma unroll
    for (int o = 1; o < 32; o <<= 1) {
        int t = __shfl_up_sync(0xffffffffu, x, o);
        if (lane >= o) x += t;
    }
    if (lane == 31) ws[wid] = x;
    __syncthreads();
    int add = 0;
    for (int w0 = 0; w0 < wid; w0++) add += ws[w0];
    int incl = add + x;
    d_blocksum[threadIdx.x] = incl - v;
    if ((int)threadIdx.x == nb - 1) d_total = incl;
}
__global__ void scan_add_kernel(int n) {
    int i = blockIdx.x * 1024 + threadIdx.x;
    if (i < n) d_rowptr[i] += d_blocksum[blockIdx.x];
    else if (i == n) d_rowptr[n] = d_total;
}
__global__ void fill_self_kernel(int n) {
    int i = blockIdx.x * blockDim.x + threadIdx.x;
    if (i < n) {
        int r = d_rowptr[i];
        d_col[r] = i;
        d_cur[i] = r + 1;
    }
}
__global__ void scatter_edges_kernel(const int* __restrict__ src,
                                     const int* __restrict__ dst, int E) {
    int e = blockIdx.x * blockDim.x + threadIdx.x;
    if (e < E) {
        int p = atomicAdd(&d_cur[dst[e]], 1);
        d_col[p] = src[e];
    }
}

// ---------------- TF32 tensor-core GEMM: C[n,O] = A[n,I] @ W[O,I]^T --------------
// 128x64 block tile, BK=32, 256 threads = 8 warps (4m x 2n), warp tile 32x32.
#define GLD 36   // padded smem row stride (floats) for BK=32
__global__ void gemm_tf32_kernel(const float* __restrict__ A, const float* __restrict__ W,
                                 float* __restrict__ C, int n, int I, int O) {
    __shared__ float As[128 * GLD];
    __shared__ float Bs[64 * GLD];
    int tid = threadIdx.x;
    int w = tid >> 5;
    int wm = w & 3, wn = w >> 2;
    int bm = blockIdx.y * 128, bn = blockIdx.x * 64;

    wmma::fragment<wmma::accumulator, 16, 16, 8, float> acc[2][2];
#pragma unroll
    for (int i = 0; i < 2; i++)
#pragma unroll
        for (int j = 0; j < 2; j++) wmma::fill_fragment(acc[i][j], 0.f);

    for (int k0 = 0; k0 < I; k0 += 32) {
        // load A tile: 128 rows x 32 floats = 1024 float4 -> 4 per thread
#pragma unroll
        for (int t = 0; t < 4; t++) {
            int idx = tid * 4 + t;           // 0..1023
            int r = idx >> 3, kq = (idx & 7) * 4;
            int ar = bm + r;
            float4 av = make_float4(0.f, 0.f, 0.f, 0.f);
            if (ar < n) av = *(const float4*)(A + (size_t)ar * I + k0 + kq);
            *(float4*)(As + r * GLD + kq) = av;
        }
        // load B tile: 64 rows x 32 floats = 512 float4 -> 2 per thread
#pragma unroll
        for (int t = 0; t < 2; t++) {
            int idx = tid * 2 + t;           // 0..511
            int r = idx >> 3, kq = (idx & 7) * 4;
            int br = bn + r;
            float4 bv = make_float4(0.f, 0.f, 0.f, 0.f);
            if (br < O) bv = *(const float4*)(W + (size_t)br * I + k0 + kq);
            *(float4*)(Bs + r * GLD + kq) = bv;
        }
        __syncthreads();
#pragma unroll
        for (int kk = 0; kk < 32; kk += 8) {
            wmma::fragment<wmma::matrix_a, 16, 16, 8, wmma::precision::tf32, wmma::row_major> af[2];
            wmma::fragment<wmma::matrix_b, 16, 16, 8, wmma::precision::tf32, wmma::col_major> bf[2];
            wmma::load_matrix_sync(af[0], As + (wm * 32) * GLD + kk, GLD);
            wmma::load_matrix_sync(af[1], As + (wm * 32 + 16) * GLD + kk, GLD);
            wmma::load_matrix_sync(bf[0], Bs + (wn * 32) * GLD + kk, GLD);
            wmma::load_matrix_sync(bf[1], Bs + (wn * 32 + 16) * GLD + kk, GLD);
            // NOTE: intentionally no __float_to_tf32 rounding; HW truncation is
            // within our (4 orders of magnitude) precision budget.
#pragma unroll
            for (int i = 0; i < 2; i++)
#pragma unroll
                for (int j = 0; j < 2; j++)
                    wmma::mma_sync(acc[i][j], af[i], bf[j], acc[i][j]);
        }
        __syncthreads();
    }
#pragma unroll
    for (int i = 0; i < 2; i++) {
        int r0 = bm + wm * 32 + i * 16;
        if (r0 >= n) continue;               // n % 16 == 0 -> frag fully valid
#pragma unroll
        for (int j = 0; j < 2; j++) {
            int c0 = bn + wn * 32 + j * 16;
            if (c0 < O)
                wmma::store_matrix_sync(C + (size_t)r0 * O + c0, acc[i][j], O,
                                        wmma::mem_row_major);
        }
    }
}

// ---------------- alpha_src / alpha_dst per node (warp per row, float4) ----------
__global__ void alpha_kernel(const float* __restrict__ h, const float* __restrict__ a_s,
                             const float* __restrict__ a_d, int n, int O) {
    int warp = (blockIdx.x * blockDim.x + threadIdx.x) >> 5;
    int lane = threadIdx.x & 31;
    if (warp >= n) return;
    const float4* row = (const float4*)(h + (size_t)warp * O);
    const float4* as4 = (const float4*)a_s;
    const float4* ad4 = (const float4*)a_d;
    int c4 = O >> 2;
    float sa = 0.f, sd = 0.f;
    for (int c = lane; c < c4; c += 32) {
        float4 hv = row[c], av = as4[c], dv = ad4[c];
        sa += hv.x * av.x + hv.y * av.y + hv.z * av.z + hv.w * av.w;
        sd += hv.x * dv.x + hv.y * dv.y + hv.z * dv.z + hv.w * dv.w;
    }
#pragma unroll
    for (int o = 16; o; o >>= 1) {
        sa += __shfl_xor_sync(0xffffffffu, sa, o);
        sd += __shfl_xor_sync(0xffffffffu, sd, o);
    }
    if (lane == 0) { d_as[warp] = sa; d_ad[warp] = sd; }
}

// ---------------- GAT aggregate: warp per dst node, CSR gather, vectorized -------
template <int CPL, bool ZPOOL>   // channels per lane = O/32
__global__ void gat_agg_kernel(const float* __restrict__ hlin,
                               const float* __restrict__ bias,
                               float* __restrict__ out, int n, int O) {
    int gt = blockIdx.x * blockDim.x + threadIdx.x;
    if (ZPOOL) {   // zero pooling buffers for the upcoming pool kernel
        if (gt < GG * 32) d_gsum[gt] = 0.f;
        if (gt < GG) d_gcnt[gt] = 0.f;
    }
    int warp = gt >> 5;
    int lane = threadIdx.x & 31;
    if (warp >= n) return;
    int s = d_rowptr[warp];
    int e = d_rowptr[warp + 1];
    float adi = d_ad[warp];

    float m = -1e30f;
    for (int p = s + lane; p < e; p += 32) {
        float v = d_as[d_col[p]] + adi;
        v = v > 0.f ? v : 0.2f * v;
        m = fmaxf(m, v);
    }
#pragma unroll
    for (int o = 16; o; o >>= 1) m = fmaxf(m, __shfl_xor_sync(0xffffffffu, m, o));

    float den = 0.f;
    float acc[CPL];
#pragma unroll
    for (int c = 0; c < CPL; c++) acc[c] = 0.f;

    for (int p0 = s; p0 < e; p0 += 32) {
        int p = p0 + lane;
        float w = 0.f;
        int src = 0;
        if (p < e) {
            src = d_col[p];
            float v = d_as[src] + adi;
            v = v > 0.f ? v : 0.2f * v;
            w = __expf(v - m);
            den += w;
        }
        int cnt = min(32, e - p0);
        for (int q = 0; q < cnt; q++) {
            float wq = __shfl_sync(0xffffffffu, w, q);
            int   sq = __shfl_sync(0xffffffffu, src, q);
            const float* row = hlin + (size_t)sq * O;
            if (CPL == 1) {
                acc[0] += wq * row[lane];
            } else if (CPL == 2) {
                float2 v2 = ((const float2*)row)[lane];
                acc[0] += wq * v2.x; acc[1] += wq * v2.y;
            } else if (CPL == 4) {
                float4 v4 = ((const float4*)row)[lane];
                acc[0] += wq * v4.x; acc[1] += wq * v4.y;
                acc[2] += wq * v4.z; acc[3] += wq * v4.w;
            } else {   // CPL == 8
                float4 v4 = ((const float4*)row)[lane];
                float4 u4 = ((const float4*)row)[lane + 32];
                acc[0] += wq * v4.x; acc[1] += wq * v4.y;
                acc[2] += wq * v4.z; acc[3] += wq * v4.w;
                acc[4] += wq * u4.x; acc[5] += wq * u4.y;
                acc[6] += wq * u4.z; acc[7] += wq * u4.w;
            }
        }
    }
#pragma unroll
    for (int o = 16; o; o >>= 1) den += __shfl_xor_sync(0xffffffffu, den, o);
    float inv = 1.f / den;

    float* orow = out + (size_t)warp * O;
    if (CPL == 1) {
        float v = acc[0] * inv + bias[lane];
        orow[lane] = v > 0.f ? v : 0.f;
    } else if (CPL == 2) {
        float2 b2 = ((const float2*)bias)[lane];
        float2 r2;
        r2.x = acc[0] * inv + b2.x; r2.x = r2.x > 0.f ? r2.x : 0.f;
        r2.y = acc[1] * inv + b2.y; r2.y = r2.y > 0.f ? r2.y : 0.f;
        ((float2*)orow)[lane] = r2;
    } else if (CPL == 4) {
        float4 b4 = ((const float4*)bias)[lane];
        float4 r4;
        r4.x = acc[0] * inv + b4.x; r4.x = r4.x > 0.f ? r4.x : 0.f;
        r4.y = acc[1] * inv + b4.y; r4.y = r4.y > 0.f ? r4.y : 0.f;
        r4.z = acc[2] * inv + b4.z; r4.z = r4.z > 0.f ? r4.z : 0.f;
        r4.w = acc[3] * inv + b4.w; r4.w = r4.w > 0.f ? r4.w : 0.f;
        ((float4*)orow)[lane] = r4;
    } else {
        float4 b4 = ((const float4*)bias)[lane];
        float4 c4 = ((const float4*)bias)[lane + 32];
        float4 r4, s4;
        r4.x = acc[0] * inv + b4.x; r4.x = r4.x > 0.f ? r4.x : 0.f;
        r4.y = acc[1] * inv + b4.y; r4.y = r4.y > 0.f ? r4.y : 0.f;
        r4.z = acc[2] * inv + b4.z; r4.z = r4.z > 0.f ? r4.z : 0.f;
        r4.w = acc[3] * inv + b4.w; r4.w = r4.w > 0.f ? r4.w : 0.f;
        s4.x = acc[4] * inv + c4.x; s4.x = s4.x > 0.f ? s4.x : 0.f;
        s4.y = acc[5] * inv + c4.y; s4.y = s4.y > 0.f ? s4.y : 0.f;
        s4.z = acc[6] * inv + c4.z; s4.z = s4.z > 0.f ? s4.z : 0.f;
        s4.w = acc[7] * inv + c4.w; s4.w = s4.w > 0.f ? s4.w : 0.f;
        ((float4*)orow)[lane] = r4;
        ((float4*)orow)[lane + 32] = s4;
    }
}

// ---------------- mean pooling + final linear+sigmoid ----------------------------
__global__ void pool_kernel(const float* __restrict__ h, const int* __restrict__ batch,
                            int n) {
    int warp = (blockIdx.x * blockDim.x + threadIdx.x) >> 5;
    int lane = threadIdx.x & 31;
    if (warp >= n) return;
    int b = batch[warp];
    atomicAdd(&d_gsum[b * 32 + lane], h[(size_t)warp * 32 + lane]);
    if (lane == 0) atomicAdd(&d_gcnt[b], 1.f);
}
__global__ void final_kernel(const float* __restrict__ lw, const float* __restrict__ lb,
                             float* __restrict__ out) {
    int g = blockIdx.x * blockDim.x + threadIdx.x;
    if (g >= GG) return;
    float cnt = fmaxf(d_gcnt[g], 1.f);
    float acc = lb[0];
#pragma unroll
    for (int c = 0; c < 32; c++) acc += (d_gsum[g * 32 + c] / cnt) * lw[c];
    out[g] = 1.f / (1.f + __expf(-acc));
}

// ---------------- launch ----------------------------------------------------------
extern "C" void kernel_launch(void* const* d_in, const int* in_sizes, int n_in,
                              void* d_out, int out_size) {
    const float* x     = (const float*)d_in[0];
    const int*   ei    = (const int*)d_in[1];
    const int*   batch = (const int*)d_in[2];
    const float* w1 = (const float*)d_in[3]; const float* b1 = (const float*)d_in[4];
    const float* w2 = (const float*)d_in[5]; const float* b2 = (const float*)d_in[6];
    const float* w3 = (const float*)d_in[7]; const float* b3 = (const float*)d_in[8];
    float* out = (float*)d_out;

    int n = in_sizes[0];
    int E = in_sizes[1] / 2;
    const int* src = ei;
    const int* dst = ei + E;

    float* bufA; float* bufB;
    cudaGetSymbolAddress((void**)&bufA, d_bufA);
    cudaGetSymbolAddress((void**)&bufB, d_bufB);

    const int TPB = 256;
    int warpBlocks = (n * 32 + TPB - 1) / TPB;

    mlp_kernel<<<warpBlocks, TPB>>>(x, w1, b1, w2, b2, w3, b3, bufA, n);

    init_deg_kernel<<<(n + TPB - 1) / TPB, TPB>>>(n);
    count_deg_kernel<<<(E + TPB - 1) / TPB, TPB>>>(dst, E);
    int nb = (n + 1023) / 1024;
    scan_block_kernel<<<nb, 1024>>>(n);
    scan_sums_kernel<<<1, 128>>>(nb);
    scan_add_kernel<<<(n + 1024) / 1024, 1024>>>(n);
    fill_self_kernel<<<(n + TPB - 1) / TPB, TPB>>>(n);
    scatter_edges_kernel<<<(E + TPB - 1) / TPB, TPB>>>(src, dst, E);

    struct Layer { const float *W, *as_, *ad_, *b; int I, O; };
    Layer L[5] = {
        { (const float*)d_in[9],  (const float*)d_in[10], (const float*)d_in[11], (const float*)d_in[12],  64, 128 },
        { (const float*)d_in[13], (const float*)d_in[14], (const float*)d_in[15], (const float*)d_in[16], 128, 256 },
        { (const float*)d_in[17], (const float*)d_in[18], (const float*)d_in[19], (const float*)d_in[20], 256, 128 },
        { (const float*)d_in[21], (const float*)d_in[22], (const float*)d_in[23], (const float*)d_in[24], 128,  64 },
        { (const float*)d_in[25], (const float*)d_in[26], (const float*)d_in[27], (const float*)d_in[28],  64,  32 },
    };

    for (int l = 0; l < 5; l++) {
        int I = L[l].I, O = L[l].O;
        dim3 grid((O + 63) / 64, (n + 127) / 128);
        gemm_tf32_kernel<<<grid, 256>>>(bufA, L[l].W, bufB, n, I, O);
        alpha_kernel<<<warpBlocks, TPB>>>(bufB, L[l].as_, L[l].ad_, n, O);
        switch (O >> 5) {
            case 1: gat_agg_kernel<1, true ><<<warpBlocks, TPB>>>(bufB, L[l].b, bufA, n, O); break;
            case 2: gat_agg_kernel<2, false><<<warpBlocks, TPB>>>(bufB, L[l].b, bufA, n, O); break;
            case 4: gat_agg_kernel<4, false><<<warpBlocks, TPB>>>(bufB, L[l].b, bufA, n, O); break;
            case 8: gat_agg_kernel<8, false><<<warpBlocks, TPB>>>(bufB, L[l].b, bufA, n, O); break;
        }
    }

    pool_kernel<<<warpBlocks, TPB>>>(bufA, batch, n);
    final_kernel<<<(GG + TPB - 1) / TPB, TPB>>>((const float*)d_in[29],
                                                (const float*)d_in[30], out);
}